// round 14
// baseline (speedup 1.0000x reference)
#include <cuda_runtime.h>
#include <cuda_bf16.h>

// ConvThreshold: scale-adaptive 5x5 Gaussian conv over ReLU(bev_map) + mask.
//   conv[b,y,x] = sum relu(map[y+dy,x+dx]) * e1^(dy^2+dx^2),  e1 = exp(-1/(2 s^2+eps))
// R11 = R10 (single-wave grid, RPT=4, pre-barrier exp) + packed f32x2 compute:
// pixels (0,1) and (2,3) processed as fma.rn.f32x2 pairs (sm_103a packed FMA).

#define BH 768
#define BW 768
#define NB 4

#define TX 32
#define TY 8
#define VEC 4
#define RPT 4                    // output rows per thread
#define OW (TX * VEC)            // 128 output cols per block
#define OH (TY * RPT)            // 32 output rows per block
#define TILE_W (OW + 8)          // 136 floats (x-origin = bx-4)
#define TILE_H (OH + 4)          // 36 rows   (y-origin = by-2)
#define TILE_W4 (TILE_W / 4)     // 34
#define NLOAD (TILE_H * TILE_W4) // 1224 float4s per block

typedef unsigned long long f32x2_t;

__device__ __forceinline__ f32x2_t pk2(float lo, float hi) {
    f32x2_t r;
    asm("mov.b64 %0, {%1, %2};" : "=l"(r) : "f"(lo), "f"(hi));
    return r;
}
__device__ __forceinline__ void upk2(float& lo, float& hi, f32x2_t v) {
    asm("mov.b64 {%0, %1}, %2;" : "=f"(lo), "=f"(hi) : "l"(v));
}
__device__ __forceinline__ f32x2_t add2(f32x2_t a, f32x2_t b) {
    f32x2_t r;
    asm("add.rn.f32x2 %0, %1, %2;" : "=l"(r) : "l"(a), "l"(b));
    return r;
}
__device__ __forceinline__ f32x2_t fma2(f32x2_t a, f32x2_t b, f32x2_t c) {
    f32x2_t r;
    asm("fma.rn.f32x2 %0, %1, %2, %3;" : "=l"(r) : "l"(a), "l"(b), "l"(c));
    return r;
}

__global__ __launch_bounds__(TX * TY, 4) void conv_threshold_kernel(
    const float* __restrict__ bev_map,
    const float* __restrict__ bev_scale,
    float* __restrict__ out_conv,
    float* __restrict__ out_mask)
{
    __shared__ float tile[TILE_H][TILE_W];

    const int bx = blockIdx.x * OW;
    const int by = blockIdx.y * OH;
    const int b  = blockIdx.z;
    const int tx = threadIdx.x;
    const int ty = threadIdx.y;
    const int tid = ty * TX + tx;

    const float* m = bev_map + (size_t)b * BH * BW;

    // ---- prefetch per-thread scales FIRST (DRAM latency overlaps tile fill) ----
    const int gx  = bx + tx * VEC;
    const int oy0 = by + ty * RPT;
    const size_t obase = (size_t)b * BH * BW + (size_t)oy0 * BW + gx;
    float4 s4[RPT];
#pragma unroll
    for (int o = 0; o < RPT; o++)
        s4[o] = __ldg(reinterpret_cast<const float4*>(&bev_scale[obase + (size_t)o * BW]));

    // ---- cooperative tile fill: [by-2, by+OH+2) x [bx-4, bx+OW+4), ReLU'd ----
    const bool interior = (bx >= 4) && (bx + OW + 4 <= BW) &&
                          (by >= 2) && (by + OH + 2 <= BH);
    if (interior) {
#pragma unroll
        for (int it = 0; it < 5; it++) {
            const int idx = tid + it * (TX * TY);
            if (idx < NLOAD) {
                const int ly  = idx / TILE_W4;
                const int lxv = idx - ly * TILE_W4;
                float4 v = *reinterpret_cast<const float4*>(
                    &m[(size_t)(by + ly - 2) * BW + (bx - 4 + lxv * 4)]);
                v.x = fmaxf(v.x, 0.0f); v.y = fmaxf(v.y, 0.0f);
                v.z = fmaxf(v.z, 0.0f); v.w = fmaxf(v.w, 0.0f);
                *reinterpret_cast<float4*>(&tile[ly][lxv * 4]) = v;
            }
        }
    } else {
        for (int idx = tid; idx < NLOAD; idx += TX * TY) {
            const int ly  = idx / TILE_W4;
            const int lxv = idx - ly * TILE_W4;
            const int gy  = by + ly - 2;
            const int gx0 = bx - 4 + lxv * 4;
            float4 v;
            if ((unsigned)gy < BH && gx0 >= 0 && gx0 + 3 < BW) {
                v = *reinterpret_cast<const float4*>(&m[(size_t)gy * BW + gx0]);
            } else {
                const float* row = &m[(size_t)gy * BW];
                v.x = ((unsigned)gy < BH && (unsigned)(gx0 + 0) < BW) ? row[gx0 + 0] : 0.0f;
                v.y = ((unsigned)gy < BH && (unsigned)(gx0 + 1) < BW) ? row[gx0 + 1] : 0.0f;
                v.z = ((unsigned)gy < BH && (unsigned)(gx0 + 2) < BW) ? row[gx0 + 2] : 0.0f;
                v.w = ((unsigned)gy < BH && (unsigned)(gx0 + 3) < BW) ? row[gx0 + 3] : 0.0f;
            }
            v.x = fmaxf(v.x, 0.0f); v.y = fmaxf(v.y, 0.0f);
            v.z = fmaxf(v.z, 0.0f); v.w = fmaxf(v.w, 0.0f);
            *reinterpret_cast<float4*>(&tile[ly][lxv * 4]) = v;
        }
    }

    // ---- weight exp math BEFORE the barrier; pack into f32x2 pairs ----
    // w1p[o][h] = (e1 of pixel 2h, e1 of pixel 2h+1); same for w4p with e1^4.
    f32x2_t w1p[RPT][2], w4p[RPT][2];
#pragma unroll
    for (int o = 0; o < RPT; o++) {
        float e1v[VEC], e4v[VEC];
#pragma unroll
        for (int p = 0; p < VEC; p++) {
            const float s = (p == 0) ? s4[o].x : (p == 1) ? s4[o].y
                          : (p == 2) ? s4[o].z : s4[o].w;
            const float e1 = __expf(-1.0f / (2.0f * s * s + 1e-6f));
            const float e2 = e1 * e1;
            e1v[p] = e1;
            e4v[p] = e2 * e2;
        }
        w1p[o][0] = pk2(e1v[0], e1v[1]); w1p[o][1] = pk2(e1v[2], e1v[3]);
        w4p[o][0] = pk2(e4v[0], e4v[1]); w4p[o][1] = pk2(e4v[2], e4v[3]);
    }

    __syncthreads();

    // ---- per-thread: 4 x-pixels x 4 y-rows, packed f32x2 math ----
    f32x2_t acc2[RPT][2];
#pragma unroll
    for (int o = 0; o < RPT; o++) { acc2[o][0] = 0ull; acc2[o][1] = 0ull; }

    const int c0 = tx * VEC;       // tile x-origin bx-4; pixel p tap dx -> v[2+p+dx]
    const int r0 = ty * RPT;

#pragma unroll
    for (int r = 0; r < 5 + RPT - 1; r++) {   // 8 tile rows
        // v0..v3 = a, v4..v7 = bq, v8..v11 = c
        const float4 a  = *reinterpret_cast<const float4*>(&tile[r0 + r][c0]);
        const float4 bq = *reinterpret_cast<const float4*>(&tile[r0 + r][c0 + 4]);
        const float4 c  = *reinterpret_cast<const float4*>(&tile[r0 + r][c0 + 8]);

        const f32x2_t P23 = pk2(a.z,  a.w);    // (v2,v3)
        const f32x2_t P45 = pk2(bq.x, bq.y);   // (v4,v5)
        const f32x2_t P67 = pk2(bq.z, bq.w);   // (v6,v7)
        const f32x2_t P89 = pk2(c.x,  c.y);    // (v8,v9)
        const f32x2_t P34 = pk2(a.w,  bq.x);   // (v3,v4)
        const f32x2_t P56 = pk2(bq.y, bq.z);   // (v5,v6)
        const f32x2_t P78 = pk2(bq.w, c.x);    // (v7,v8)

        // x-pair sums per pixel pair: a04 = v[2+p]+v[6+p], a13 = v[3+p]+v[5+p], a2 = v[4+p]
        const f32x2_t a04_0 = add2(P23, P67);  // pixels 0,1
        const f32x2_t a04_1 = add2(P45, P89);  // pixels 2,3
        const f32x2_t a13_0 = add2(P34, P56);
        const f32x2_t a13_1 = add2(P56, P78);
        const f32x2_t a2_0  = P45;
        const f32x2_t a2_1  = P67;

#pragma unroll
        for (int o = 0; o < RPT; o++) {
            const int k = r - o;               // tap index for output row o
            if (k >= 0 && k <= 4) {
                const int ady = (k < 2) ? (2 - k) : (k - 2);   // |dy| in {0,1,2}
                const f32x2_t rs0 = fma2(w4p[o][0], a04_0,
                                    fma2(w1p[o][0], a13_0, a2_0));
                const f32x2_t rs1 = fma2(w4p[o][1], a04_1,
                                    fma2(w1p[o][1], a13_1, a2_1));
                if (ady == 0) {
                    acc2[o][0] = add2(acc2[o][0], rs0);
                    acc2[o][1] = add2(acc2[o][1], rs1);
                } else if (ady == 1) {
                    acc2[o][0] = fma2(rs0, w1p[o][0], acc2[o][0]);
                    acc2[o][1] = fma2(rs1, w1p[o][1], acc2[o][1]);
                } else {
                    acc2[o][0] = fma2(rs0, w4p[o][0], acc2[o][0]);
                    acc2[o][1] = fma2(rs1, w4p[o][1], acc2[o][1]);
                }
            }
        }
    }

#pragma unroll
    for (int o = 0; o < RPT; o++) {
        float a0, a1, a2f, a3;
        upk2(a0, a1, acc2[o][0]);
        upk2(a2f, a3, acc2[o][1]);
        float4 conv4 = make_float4(a0, a1, a2f, a3);
        float4 mask4 = make_float4(a0  >= 0.5f ? 1.0f : 0.0f,
                                   a1  >= 0.5f ? 1.0f : 0.0f,
                                   a2f >= 0.5f ? 1.0f : 0.0f,
                                   a3  >= 0.5f ? 1.0f : 0.0f);
        *reinterpret_cast<float4*>(&out_conv[obase + (size_t)o * BW]) = conv4;
        *reinterpret_cast<float4*>(&out_mask[obase + (size_t)o * BW]) = mask4;
    }
}

extern "C" void kernel_launch(void* const* d_in, const int* in_sizes, int n_in,
                              void* d_out, int out_size)
{
    const float* bev_map   = (const float*)d_in[0];
    const float* bev_scale = (const float*)d_in[1];
    float* out = (float*)d_out;

    float* out_conv = out;
    float* out_mask = out + (size_t)NB * BH * BW;

    dim3 block(TX, TY);
    dim3 grid(BW / OW, BH / OH, NB);   // 6 x 24 x 4 = 576 blocks = one wave @ occ 4
    conv_threshold_kernel<<<grid, block>>>(bev_map, bev_scale, out_conv, out_mask);
}

// round 15
// speedup vs baseline: 1.3284x; 1.3284x over previous
#include <cuda_runtime.h>
#include <cuda_bf16.h>

// ConvThreshold: scale-adaptive 5x5 Gaussian conv over ReLU(bev_map) + mask.
//   conv[b,y,x] = sum relu(map[y+dy,x+dx]) * e1^(dy^2+dx^2),  e1 = exp(-1/(2 s^2+eps))
// Separable weights. Single-wave grid (576 blocks = 148 SMs x 4 CTAs),
// RPT=4 rows/thread, interior fast-path tile fill, pre-barrier scale/exp.
// (R15 = verbatim revert to the measured-best R10; f32x2 variant regressed.)

#define BH 768
#define BW 768
#define NB 4

#define TX 32
#define TY 8
#define VEC 4
#define RPT 4                    // output rows per thread
#define OW (TX * VEC)            // 128 output cols per block
#define OH (TY * RPT)            // 32 output rows per block
#define TILE_W (OW + 8)          // 136 floats (x-origin = bx-4)
#define TILE_H (OH + 4)          // 36 rows   (y-origin = by-2)
#define TILE_W4 (TILE_W / 4)     // 34
#define NLOAD (TILE_H * TILE_W4) // 1224 float4s per block

__global__ __launch_bounds__(TX * TY, 4) void conv_threshold_kernel(
    const float* __restrict__ bev_map,
    const float* __restrict__ bev_scale,
    float* __restrict__ out_conv,
    float* __restrict__ out_mask)
{
    __shared__ float tile[TILE_H][TILE_W];

    const int bx = blockIdx.x * OW;
    const int by = blockIdx.y * OH;
    const int b  = blockIdx.z;
    const int tx = threadIdx.x;
    const int ty = threadIdx.y;
    const int tid = ty * TX + tx;

    const float* m = bev_map + (size_t)b * BH * BW;

    // ---- prefetch per-thread scales FIRST (DRAM latency overlaps tile fill) ----
    const int gx  = bx + tx * VEC;
    const int oy0 = by + ty * RPT;
    const size_t obase = (size_t)b * BH * BW + (size_t)oy0 * BW + gx;
    float4 s4[RPT];
#pragma unroll
    for (int o = 0; o < RPT; o++)
        s4[o] = __ldg(reinterpret_cast<const float4*>(&bev_scale[obase + (size_t)o * BW]));

    // ---- cooperative tile fill: [by-2, by+OH+2) x [bx-4, bx+OW+4), ReLU'd ----
    const bool interior = (bx >= 4) && (bx + OW + 4 <= BW) &&
                          (by >= 2) && (by + OH + 2 <= BH);
    if (interior) {
#pragma unroll
        for (int it = 0; it < 5; it++) {
            const int idx = tid + it * (TX * TY);
            if (idx < NLOAD) {
                const int ly  = idx / TILE_W4;
                const int lxv = idx - ly * TILE_W4;
                float4 v = *reinterpret_cast<const float4*>(
                    &m[(size_t)(by + ly - 2) * BW + (bx - 4 + lxv * 4)]);
                v.x = fmaxf(v.x, 0.0f); v.y = fmaxf(v.y, 0.0f);
                v.z = fmaxf(v.z, 0.0f); v.w = fmaxf(v.w, 0.0f);
                *reinterpret_cast<float4*>(&tile[ly][lxv * 4]) = v;
            }
        }
    } else {
        for (int idx = tid; idx < NLOAD; idx += TX * TY) {
            const int ly  = idx / TILE_W4;
            const int lxv = idx - ly * TILE_W4;
            const int gy  = by + ly - 2;
            const int gx0 = bx - 4 + lxv * 4;
            float4 v;
            if ((unsigned)gy < BH && gx0 >= 0 && gx0 + 3 < BW) {
                v = *reinterpret_cast<const float4*>(&m[(size_t)gy * BW + gx0]);
            } else {
                const float* row = &m[(size_t)gy * BW];
                v.x = ((unsigned)gy < BH && (unsigned)(gx0 + 0) < BW) ? row[gx0 + 0] : 0.0f;
                v.y = ((unsigned)gy < BH && (unsigned)(gx0 + 1) < BW) ? row[gx0 + 1] : 0.0f;
                v.z = ((unsigned)gy < BH && (unsigned)(gx0 + 2) < BW) ? row[gx0 + 2] : 0.0f;
                v.w = ((unsigned)gy < BH && (unsigned)(gx0 + 3) < BW) ? row[gx0 + 3] : 0.0f;
            }
            v.x = fmaxf(v.x, 0.0f); v.y = fmaxf(v.y, 0.0f);
            v.z = fmaxf(v.z, 0.0f); v.w = fmaxf(v.w, 0.0f);
            *reinterpret_cast<float4*>(&tile[ly][lxv * 4]) = v;
        }
    }

    // ---- weight exp math BEFORE the barrier (overlaps STS drain / bar wait) ----
    float e1w[RPT][VEC], e4w[RPT][VEC];
#pragma unroll
    for (int o = 0; o < RPT; o++) {
#pragma unroll
        for (int p = 0; p < VEC; p++) {
            const float s = (p == 0) ? s4[o].x : (p == 1) ? s4[o].y
                          : (p == 2) ? s4[o].z : s4[o].w;
            const float e1 = __expf(-1.0f / (2.0f * s * s + 1e-6f));
            const float e2 = e1 * e1;
            e1w[o][p] = e1;
            e4w[o][p] = e2 * e2;
        }
    }

    __syncthreads();

    // ---- per-thread: 4 x-pixels (gx..gx+3) x 4 y-rows (oy0..oy0+3) ----
    float acc[RPT][VEC];
#pragma unroll
    for (int o = 0; o < RPT; o++)
#pragma unroll
        for (int p = 0; p < VEC; p++) acc[o][p] = 0.0f;

    const int c0 = tx * VEC;       // pixel p tap dx -> v[2+p+dx] (tile x-origin bx-4)
    const int r0 = ty * RPT;       // tile row of out row0's dy=0 tap

#pragma unroll
    for (int r = 0; r < 5 + RPT - 1; r++) {   // 8 tile rows
        const float4 a  = *reinterpret_cast<const float4*>(&tile[r0 + r][c0]);
        const float4 bq = *reinterpret_cast<const float4*>(&tile[r0 + r][c0 + 4]);
        const float4 c  = *reinterpret_cast<const float4*>(&tile[r0 + r][c0 + 8]);
        const float v[12] = {a.x, a.y, a.z, a.w, bq.x, bq.y, bq.z, bq.w,
                             c.x, c.y, c.z, c.w};

        // weight-independent x-pair sums, shared by all output rows
        float a04[VEC], a13[VEC], a2[VEC];
#pragma unroll
        for (int p = 0; p < VEC; p++) {
            a04[p] = v[2 + p] + v[6 + p];
            a13[p] = v[3 + p] + v[5 + p];
            a2[p]  = v[4 + p];
        }

#pragma unroll
        for (int o = 0; o < RPT; o++) {
            const int k = r - o;               // tap index for output row o
            if (k >= 0 && k <= 4) {
                const int ady = (k < 2) ? (2 - k) : (k - 2);   // |dy| in {0,1,2}
#pragma unroll
                for (int p = 0; p < VEC; p++) {
                    const float rs = fmaf(e4w[o][p], a04[p],
                                     fmaf(e1w[o][p], a13[p], a2[p]));
                    if (ady == 0)      acc[o][p] += rs;
                    else if (ady == 1) acc[o][p] = fmaf(rs, e1w[o][p], acc[o][p]);
                    else               acc[o][p] = fmaf(rs, e4w[o][p], acc[o][p]);
                }
            }
        }
    }

#pragma unroll
    for (int o = 0; o < RPT; o++) {
        float4 conv4 = make_float4(acc[o][0], acc[o][1], acc[o][2], acc[o][3]);
        float4 mask4 = make_float4(acc[o][0] >= 0.5f ? 1.0f : 0.0f,
                                   acc[o][1] >= 0.5f ? 1.0f : 0.0f,
                                   acc[o][2] >= 0.5f ? 1.0f : 0.0f,
                                   acc[o][3] >= 0.5f ? 1.0f : 0.0f);
        *reinterpret_cast<float4*>(&out_conv[obase + (size_t)o * BW]) = conv4;
        *reinterpret_cast<float4*>(&out_mask[obase + (size_t)o * BW]) = mask4;
    }
}

extern "C" void kernel_launch(void* const* d_in, const int* in_sizes, int n_in,
                              void* d_out, int out_size)
{
    const float* bev_map   = (const float*)d_in[0];
    const float* bev_scale = (const float*)d_in[1];
    float* out = (float*)d_out;

    float* out_conv = out;
    float* out_mask = out + (size_t)NB * BH * BW;

    dim3 block(TX, TY);
    dim3 grid(BW / OW, BH / OH, NB);   // 6 x 24 x 4 = 576 blocks = one wave @ occ 4
    conv_threshold_kernel<<<grid, block>>>(bev_map, bev_scale, out_conv, out_mask);
}

// round 16
// speedup vs baseline: 1.5940x; 1.2000x over previous
#include <cuda_runtime.h>
#include <cuda_bf16.h>

// ConvThreshold: scale-adaptive 5x5 Gaussian conv over ReLU(bev_map) + mask.
//   conv[b,y,x] = sum relu(map[y+dy,x+dx]) * e1^(dy^2+dx^2),  e1 = exp(-1/(2 s^2+eps))
// R16: same per-thread work as R10 (VEC=4, RPT=4, separable weights, pre-barrier
// exp) but 128-thread CTAs at 8 CTAs/SM: independent small barrier domains let
// fill stalls of one CTA overlap compute of its SM neighbors. Single wave:
// grid 6x48x4 = 1152 <= 148*8.

#define BH 768
#define BW 768
#define NB 4

#define TX 32
#define TY 4
#define NTHR (TX * TY)           // 128
#define VEC 4
#define RPT 4                    // output rows per thread
#define OW (TX * VEC)            // 128 output cols per block
#define OH (TY * RPT)            // 16 output rows per block
#define TILE_W (OW + 8)          // 136 floats (x-origin = bx-4)
#define TILE_H (OH + 4)          // 20 rows   (y-origin = by-2)
#define TILE_W4 (TILE_W / 4)     // 34
#define NLOAD (TILE_H * TILE_W4) // 680 float4s per block

__global__ __launch_bounds__(NTHR, 8) void conv_threshold_kernel(
    const float* __restrict__ bev_map,
    const float* __restrict__ bev_scale,
    float* __restrict__ out_conv,
    float* __restrict__ out_mask)
{
    __shared__ float tile[TILE_H][TILE_W];

    const int bx = blockIdx.x * OW;
    const int by = blockIdx.y * OH;
    const int b  = blockIdx.z;
    const int tx = threadIdx.x;
    const int ty = threadIdx.y;
    const int tid = ty * TX + tx;

    const float* m = bev_map + (size_t)b * BH * BW;

    // ---- prefetch per-thread scales FIRST (DRAM latency overlaps tile fill) ----
    const int gx  = bx + tx * VEC;
    const int oy0 = by + ty * RPT;
    const size_t obase = (size_t)b * BH * BW + (size_t)oy0 * BW + gx;
    float4 s4[RPT];
#pragma unroll
    for (int o = 0; o < RPT; o++)
        s4[o] = __ldg(reinterpret_cast<const float4*>(&bev_scale[obase + (size_t)o * BW]));

    // ---- cooperative tile fill: [by-2, by+OH+2) x [bx-4, bx+OW+4), ReLU'd ----
    const bool interior = (bx >= 4) && (bx + OW + 4 <= BW) &&
                          (by >= 2) && (by + OH + 2 <= BH);
    if (interior) {
#pragma unroll
        for (int it = 0; it < 6; it++) {
            const int idx = tid + it * NTHR;
            if (idx < NLOAD) {
                const int ly  = idx / TILE_W4;
                const int lxv = idx - ly * TILE_W4;
                float4 v = *reinterpret_cast<const float4*>(
                    &m[(size_t)(by + ly - 2) * BW + (bx - 4 + lxv * 4)]);
                v.x = fmaxf(v.x, 0.0f); v.y = fmaxf(v.y, 0.0f);
                v.z = fmaxf(v.z, 0.0f); v.w = fmaxf(v.w, 0.0f);
                *reinterpret_cast<float4*>(&tile[ly][lxv * 4]) = v;
            }
        }
    } else {
        for (int idx = tid; idx < NLOAD; idx += NTHR) {
            const int ly  = idx / TILE_W4;
            const int lxv = idx - ly * TILE_W4;
            const int gy  = by + ly - 2;
            const int gx0 = bx - 4 + lxv * 4;
            float4 v;
            if ((unsigned)gy < BH && gx0 >= 0 && gx0 + 3 < BW) {
                v = *reinterpret_cast<const float4*>(&m[(size_t)gy * BW + gx0]);
            } else {
                const float* row = &m[(size_t)gy * BW];
                v.x = ((unsigned)gy < BH && (unsigned)(gx0 + 0) < BW) ? row[gx0 + 0] : 0.0f;
                v.y = ((unsigned)gy < BH && (unsigned)(gx0 + 1) < BW) ? row[gx0 + 1] : 0.0f;
                v.z = ((unsigned)gy < BH && (unsigned)(gx0 + 2) < BW) ? row[gx0 + 2] : 0.0f;
                v.w = ((unsigned)gy < BH && (unsigned)(gx0 + 3) < BW) ? row[gx0 + 3] : 0.0f;
            }
            v.x = fmaxf(v.x, 0.0f); v.y = fmaxf(v.y, 0.0f);
            v.z = fmaxf(v.z, 0.0f); v.w = fmaxf(v.w, 0.0f);
            *reinterpret_cast<float4*>(&tile[ly][lxv * 4]) = v;
        }
    }

    // ---- weight exp math BEFORE the barrier (overlaps fill latency) ----
    float e1w[RPT][VEC], e4w[RPT][VEC];
#pragma unroll
    for (int o = 0; o < RPT; o++) {
#pragma unroll
        for (int p = 0; p < VEC; p++) {
            const float s = (p == 0) ? s4[o].x : (p == 1) ? s4[o].y
                          : (p == 2) ? s4[o].z : s4[o].w;
            const float e1 = __expf(-1.0f / (2.0f * s * s + 1e-6f));
            const float e2 = e1 * e1;
            e1w[o][p] = e1;
            e4w[o][p] = e2 * e2;
        }
    }

    __syncthreads();

    // ---- per-thread: 4 x-pixels (gx..gx+3) x 4 y-rows (oy0..oy0+3) ----
    float acc[RPT][VEC];
#pragma unroll
    for (int o = 0; o < RPT; o++)
#pragma unroll
        for (int p = 0; p < VEC; p++) acc[o][p] = 0.0f;

    const int c0 = tx * VEC;       // pixel p tap dx -> v[2+p+dx] (tile x-origin bx-4)
    const int r0 = ty * RPT;       // tile row of out row0's dy=0 tap

#pragma unroll
    for (int r = 0; r < 5 + RPT - 1; r++) {   // 8 tile rows
        const float4 a  = *reinterpret_cast<const float4*>(&tile[r0 + r][c0]);
        const float4 bq = *reinterpret_cast<const float4*>(&tile[r0 + r][c0 + 4]);
        const float4 c  = *reinterpret_cast<const float4*>(&tile[r0 + r][c0 + 8]);
        const float v[12] = {a.x, a.y, a.z, a.w, bq.x, bq.y, bq.z, bq.w,
                             c.x, c.y, c.z, c.w};

        // weight-independent x-pair sums, shared by all output rows
        float a04[VEC], a13[VEC], a2[VEC];
#pragma unroll
        for (int p = 0; p < VEC; p++) {
            a04[p] = v[2 + p] + v[6 + p];
            a13[p] = v[3 + p] + v[5 + p];
            a2[p]  = v[4 + p];
        }

#pragma unroll
        for (int o = 0; o < RPT; o++) {
            const int k = r - o;               // tap index for output row o
            if (k >= 0 && k <= 4) {
                const int ady = (k < 2) ? (2 - k) : (k - 2);   // |dy| in {0,1,2}
#pragma unroll
                for (int p = 0; p < VEC; p++) {
                    const float rs = fmaf(e4w[o][p], a04[p],
                                     fmaf(e1w[o][p], a13[p], a2[p]));
                    if (ady == 0)      acc[o][p] += rs;
                    else if (ady == 1) acc[o][p] = fmaf(rs, e1w[o][p], acc[o][p]);
                    else               acc[o][p] = fmaf(rs, e4w[o][p], acc[o][p]);
                }
            }
        }
    }

#pragma unroll
    for (int o = 0; o < RPT; o++) {
        float4 conv4 = make_float4(acc[o][0], acc[o][1], acc[o][2], acc[o][3]);
        float4 mask4 = make_float4(acc[o][0] >= 0.5f ? 1.0f : 0.0f,
                                   acc[o][1] >= 0.5f ? 1.0f : 0.0f,
                                   acc[o][2] >= 0.5f ? 1.0f : 0.0f,
                                   acc[o][3] >= 0.5f ? 1.0f : 0.0f);
        *reinterpret_cast<float4*>(&out_conv[obase + (size_t)o * BW]) = conv4;
        *reinterpret_cast<float4*>(&out_mask[obase + (size_t)o * BW]) = mask4;
    }
}

extern "C" void kernel_launch(void* const* d_in, const int* in_sizes, int n_in,
                              void* d_out, int out_size)
{
    const float* bev_map   = (const float*)d_in[0];
    const float* bev_scale = (const float*)d_in[1];
    float* out = (float*)d_out;

    float* out_conv = out;
    float* out_mask = out + (size_t)NB * BH * BW;

    dim3 block(TX, TY);
    dim3 grid(BW / OW, BH / OH, NB);   // 6 x 48 x 4 = 1152 blocks <= 148*8 = one wave
    conv_threshold_kernel<<<grid, block>>>(bev_map, bev_scale, out_conv, out_mask);
}